// round 1
// baseline (speedup 1.0000x reference)
#include <cuda_runtime.h>

// Problem constants (shapes fixed by the reference: N=16384, M=1024, D=1024).
#define D_DIM 1024
#define M_DIM 1024

#define BM 128
#define BN 128
#define BK 8
#define NT (D_DIM / BK)   // 128 k-tiles

// Scratch: per-prototype squared norms. __device__ global (no allocation).
__device__ __align__(16) float g_p2[M_DIM];

// ---------------------------------------------------------------------------
// Kernel 0: p2[m] = sum_d proto[m,d]^2   (1024 blocks x 256 threads)
// ---------------------------------------------------------------------------
__global__ __launch_bounds__(256) void p2_kernel(const float* __restrict__ proto) {
    const int m = blockIdx.x;
    const float4* row = reinterpret_cast<const float4*>(proto + (size_t)m * D_DIM);
    float4 v = row[threadIdx.x];                 // 256 * 4 = 1024 elements
    float s = v.x * v.x + v.y * v.y + v.z * v.z + v.w * v.w;

    __shared__ float red[32];
    #pragma unroll
    for (int o = 16; o; o >>= 1) s += __shfl_xor_sync(0xffffffffu, s, o);
    if ((threadIdx.x & 31) == 0) red[threadIdx.x >> 5] = s;
    __syncthreads();
    if (threadIdx.x < 32) {
        s = (threadIdx.x < 8) ? red[threadIdx.x] : 0.0f;
        #pragma unroll
        for (int o = 4; o; o >>= 1) s += __shfl_xor_sync(0xffffffffu, s, o);
        if (threadIdx.x == 0) g_p2[m] = s;
    }
}

// ---------------------------------------------------------------------------
// Kernel 1: qp[n,m] = sum_d Q[n,d] * P[m,d]  -> written to out (logit scratch)
// 128x128x8 double-buffered SGEMM, 256 threads, 8x8 microtile (2x 4-wide).
// ---------------------------------------------------------------------------
__global__ __launch_bounds__(256) void gemm_kernel(const float* __restrict__ Q,
                                                   const float* __restrict__ P,
                                                   float* __restrict__ out) {
    __shared__ float As[2][BK][BM];
    __shared__ float Bs[2][BK][BN];

    const int tid  = threadIdx.x;
    const int brow = blockIdx.y * BM;
    const int bcol = blockIdx.x * BN;

    // Global-load mapping: 256 float4s cover a 128x8 tile (2 float4 per row).
    const int lrow = tid >> 1;           // 0..127
    const int lcol = (tid & 1) << 2;     // 0 or 4

    const float* Ag = Q + (size_t)(brow + lrow) * D_DIM + lcol;
    const float* Bg = P + (size_t)(bcol + lrow) * D_DIM + lcol;

    // Microtile mapping: 16x16 thread grid; each thread owns rows
    // {ty*4..+3, 64+ty*4..+3} x cols {tx*4..+3, 64+tx*4..+3}  (conflict-free LDS.128)
    const int ty = tid >> 4;
    const int tx = tid & 15;

    float acc[8][8];
    #pragma unroll
    for (int i = 0; i < 8; i++)
        #pragma unroll
        for (int j = 0; j < 8; j++) acc[i][j] = 0.0f;

    // Prologue: tile 0 -> smem buffer 0 (transposed to [k][row]).
    float4 a4 = *reinterpret_cast<const float4*>(Ag);
    float4 b4 = *reinterpret_cast<const float4*>(Bg);
    int buf = 0;
    As[0][lcol + 0][lrow] = a4.x;  As[0][lcol + 1][lrow] = a4.y;
    As[0][lcol + 2][lrow] = a4.z;  As[0][lcol + 3][lrow] = a4.w;
    Bs[0][lcol + 0][lrow] = b4.x;  Bs[0][lcol + 1][lrow] = b4.y;
    Bs[0][lcol + 2][lrow] = b4.z;  Bs[0][lcol + 3][lrow] = b4.w;
    __syncthreads();

    for (int kt = 0; kt < NT; kt++) {
        float4 a4n, b4n;
        if (kt + 1 < NT) {
            a4n = *reinterpret_cast<const float4*>(Ag + (kt + 1) * BK);
            b4n = *reinterpret_cast<const float4*>(Bg + (kt + 1) * BK);
        }

        #pragma unroll
        for (int k = 0; k < BK; k++) {
            float a[8], b[8];
            *reinterpret_cast<float4*>(&a[0]) =
                *reinterpret_cast<const float4*>(&As[buf][k][ty * 4]);
            *reinterpret_cast<float4*>(&a[4]) =
                *reinterpret_cast<const float4*>(&As[buf][k][64 + ty * 4]);
            *reinterpret_cast<float4*>(&b[0]) =
                *reinterpret_cast<const float4*>(&Bs[buf][k][tx * 4]);
            *reinterpret_cast<float4*>(&b[4]) =
                *reinterpret_cast<const float4*>(&Bs[buf][k][64 + tx * 4]);
            #pragma unroll
            for (int i = 0; i < 8; i++)
                #pragma unroll
                for (int j = 0; j < 8; j++)
                    acc[i][j] = fmaf(a[i], b[j], acc[i][j]);
        }

        if (kt + 1 < NT) {
            const int nb = buf ^ 1;
            As[nb][lcol + 0][lrow] = a4n.x;  As[nb][lcol + 1][lrow] = a4n.y;
            As[nb][lcol + 2][lrow] = a4n.z;  As[nb][lcol + 3][lrow] = a4n.w;
            Bs[nb][lcol + 0][lrow] = b4n.x;  Bs[nb][lcol + 1][lrow] = b4n.y;
            Bs[nb][lcol + 2][lrow] = b4n.z;  Bs[nb][lcol + 3][lrow] = b4n.w;
            __syncthreads();
            buf = nb;
        }
    }

    // Epilogue: store raw qp (softmax pass applies 2*qp - p2).
    #pragma unroll
    for (int i = 0; i < 8; i++) {
        const int r = brow + ((i < 4) ? (ty * 4 + i) : (64 + ty * 4 + i - 4));
        float* orow = out + (size_t)r * M_DIM + bcol;
        *reinterpret_cast<float4*>(orow + tx * 4) =
            make_float4(acc[i][0], acc[i][1], acc[i][2], acc[i][3]);
        *reinterpret_cast<float4*>(orow + 64 + tx * 4) =
            make_float4(acc[i][4], acc[i][5], acc[i][6], acc[i][7]);
    }
}

// ---------------------------------------------------------------------------
// Kernel 2: in-place row softmax of s[m] = 2*qp[n,m] - p2[m] over M=1024.
// One block (256 threads) per row; float4 per thread.
// ---------------------------------------------------------------------------
__global__ __launch_bounds__(256) void softmax_kernel(float* __restrict__ out) {
    __shared__ float red[33];
    const int row = blockIdx.x;
    const int tid = threadIdx.x;
    float4* p = reinterpret_cast<float4*>(out + (size_t)row * M_DIM);

    float4 v  = p[tid];
    float4 pp = reinterpret_cast<const float4*>(g_p2)[tid];
    float s0 = 2.0f * v.x - pp.x;
    float s1 = 2.0f * v.y - pp.y;
    float s2 = 2.0f * v.z - pp.z;
    float s3 = 2.0f * v.w - pp.w;

    // --- row max ---
    float m = fmaxf(fmaxf(s0, s1), fmaxf(s2, s3));
    #pragma unroll
    for (int o = 16; o; o >>= 1) m = fmaxf(m, __shfl_xor_sync(0xffffffffu, m, o));
    if ((tid & 31) == 0) red[tid >> 5] = m;
    __syncthreads();
    if (tid < 32) {
        float t = (tid < 8) ? red[tid] : -3.4e38f;
        #pragma unroll
        for (int o = 4; o; o >>= 1) t = fmaxf(t, __shfl_xor_sync(0xffffffffu, t, o));
        if (tid == 0) red[32] = t;
    }
    __syncthreads();
    const float rmax = red[32];

    // --- exp + row sum ---
    float e0 = expf(s0 - rmax);
    float e1 = expf(s1 - rmax);
    float e2 = expf(s2 - rmax);
    float e3 = expf(s3 - rmax);
    float s = e0 + e1 + e2 + e3;
    #pragma unroll
    for (int o = 16; o; o >>= 1) s += __shfl_xor_sync(0xffffffffu, s, o);
    __syncthreads();          // red[] reuse
    if ((tid & 31) == 0) red[tid >> 5] = s;
    __syncthreads();
    if (tid < 32) {
        float t = (tid < 8) ? red[tid] : 0.0f;
        #pragma unroll
        for (int o = 4; o; o >>= 1) t += __shfl_xor_sync(0xffffffffu, t, o);
        if (tid == 0) red[32] = t;
    }
    __syncthreads();
    const float inv = 1.0f / red[32];

    p[tid] = make_float4(e0 * inv, e1 * inv, e2 * inv, e3 * inv);
}

// ---------------------------------------------------------------------------
extern "C" void kernel_launch(void* const* d_in, const int* in_sizes, int n_in,
                              void* d_out, int out_size) {
    const float* query = (const float*)d_in[0];   // [N, 1024] fp32
    const float* proto = (const float*)d_in[1];   // [1024, 1024] fp32
    float* out = (float*)d_out;                   // [N, 1024] fp32
    const int N = in_sizes[0] / D_DIM;

    p2_kernel<<<M_DIM, 256>>>(proto);

    dim3 grid(M_DIM / BN, N / BM);                // (8, 128)
    gemm_kernel<<<grid, 256>>>(query, proto, out);

    softmax_kernel<<<N, 256>>>(out);
}

// round 3
// speedup vs baseline: 2.3682x; 2.3682x over previous
#include <cuda_runtime.h>
#include <cuda_fp16.h>
#include <cstdint>

#define D_DIM 1024
#define M_DIM 1024
#define N_MAX 16384

#define BM 128
#define BN 128
#define BK 64                       // halves per k-tile = 128 bytes/row
#define STAGES 3
#define KT_PER_PASS (D_DIM / BK)    // 16
#define NPASS 3
#define TOT_TILES (NPASS * KT_PER_PASS)  // 48

#define STAGE_BYTES (BM * 128 + BN * 128)   // 32 KB (A then B)
#define SMEM_DYN_BYTES (STAGES * STAGE_BYTES)

// ---------------- static device scratch (no allocation allowed) -------------
__device__ __align__(16) float  g_p2[M_DIM];
__device__ __align__(16) __half g_qhi[(size_t)N_MAX * D_DIM];
__device__ __align__(16) __half g_qlo[(size_t)N_MAX * D_DIM];
__device__ __align__(16) __half g_phi[(size_t)M_DIM * D_DIM];
__device__ __align__(16) __half g_plo[(size_t)M_DIM * D_DIM];

// ---------------- helpers ----------------------------------------------------
__device__ __forceinline__ uint32_t smem_to_u32(const void* p) {
    uint32_t a;
    asm("{ .reg .u64 t; cvta.to.shared.u64 t, %1; cvt.u32.u64 %0, t; }" : "=r"(a) : "l"(p));
    return a;
}

__device__ __forceinline__ void cp_async16(uint32_t dst, const void* src) {
    asm volatile("cp.async.cg.shared.global [%0], [%1], 16;" :: "r"(dst), "l"(src) : "memory");
}
#define CP_COMMIT() asm volatile("cp.async.commit_group;" ::: "memory")
#define CP_WAIT(n)  asm volatile("cp.async.wait_group %0;" :: "n"(n) : "memory")

__device__ __forceinline__ void ldsm_x4(uint32_t* r, uint32_t addr) {
    asm volatile("ldmatrix.sync.aligned.m8n8.x4.shared.b16 {%0,%1,%2,%3}, [%4];"
                 : "=r"(r[0]), "=r"(r[1]), "=r"(r[2]), "=r"(r[3]) : "r"(addr));
}

__device__ __forceinline__ void mma16816(float* c, const uint32_t* a, const uint32_t* b) {
    asm volatile(
        "mma.sync.aligned.m16n8k16.row.col.f32.f16.f16.f32 "
        "{%0,%1,%2,%3}, {%4,%5,%6,%7}, {%8,%9}, {%0,%1,%2,%3};"
        : "+f"(c[0]), "+f"(c[1]), "+f"(c[2]), "+f"(c[3])
        : "r"(a[0]), "r"(a[1]), "r"(a[2]), "r"(a[3]), "r"(b[0]), "r"(b[1]));
}

// ---------------------------------------------------------------------------
// Kernel A: split fp32 -> (hi, lo) fp16 pairs for Q and P.
// ---------------------------------------------------------------------------
__global__ __launch_bounds__(256) void convert_kernel(const float* __restrict__ q,
                                                      const float* __restrict__ p, int nq) {
    const int row = blockIdx.x;
    const bool isQ = row < nq;
    const float* src = isQ ? (q + (size_t)row * D_DIM) : (p + (size_t)(row - nq) * D_DIM);
    __half* dhi = isQ ? (g_qhi + (size_t)row * D_DIM) : (g_phi + (size_t)(row - nq) * D_DIM);
    __half* dlo = isQ ? (g_qlo + (size_t)row * D_DIM) : (g_plo + (size_t)(row - nq) * D_DIM);

    float4 v = reinterpret_cast<const float4*>(src)[threadIdx.x];
    __half h0 = __float2half_rn(v.x), h1 = __float2half_rn(v.y);
    __half h2 = __float2half_rn(v.z), h3 = __float2half_rn(v.w);
    __half l0 = __float2half_rn(v.x - __half2float(h0));
    __half l1 = __float2half_rn(v.y - __half2float(h1));
    __half l2 = __float2half_rn(v.z - __half2float(h2));
    __half l3 = __float2half_rn(v.w - __half2float(h3));

    __half2 hv[2] = {__halves2half2(h0, h1), __halves2half2(h2, h3)};
    __half2 lv[2] = {__halves2half2(l0, l1), __halves2half2(l2, l3)};
    reinterpret_cast<uint2*>(dhi)[threadIdx.x] = *reinterpret_cast<uint2*>(hv);
    reinterpret_cast<uint2*>(dlo)[threadIdx.x] = *reinterpret_cast<uint2*>(lv);
}

// ---------------------------------------------------------------------------
// Kernel B: p2[m] = sum_d proto[m,d]^2 (exact fp32)
// ---------------------------------------------------------------------------
__global__ __launch_bounds__(256) void p2_kernel(const float* __restrict__ proto) {
    const int m = blockIdx.x;
    float4 v = reinterpret_cast<const float4*>(proto + (size_t)m * D_DIM)[threadIdx.x];
    float s = v.x * v.x + v.y * v.y + v.z * v.z + v.w * v.w;
    __shared__ float red[32];
    #pragma unroll
    for (int o = 16; o; o >>= 1) s += __shfl_xor_sync(0xffffffffu, s, o);
    if ((threadIdx.x & 31) == 0) red[threadIdx.x >> 5] = s;
    __syncthreads();
    if (threadIdx.x < 32) {
        s = (threadIdx.x < 8) ? red[threadIdx.x] : 0.0f;
        #pragma unroll
        for (int o = 4; o; o >>= 1) s += __shfl_xor_sync(0xffffffffu, s, o);
        if (threadIdx.x == 0) g_p2[m] = s;
    }
}

// ---------------------------------------------------------------------------
// Kernel C: HMMA GEMM.  qp = Qhi*Phi^T + Qhi*Plo^T + Qlo*Phi^T  -> out
// 128x128 CTA tile, BK=64, 3-stage cp.async pipeline, mma.sync m16n8k16,
// XOR-swizzled smem (128B rows), conflict-free ldmatrix.
// ---------------------------------------------------------------------------
struct LoadSlots { uint32_t dst[4]; int src[4]; };

__device__ __forceinline__ void load_tile(int t, uint32_t smem0,
                                          const __half* const* passA,
                                          const __half* const* passB,
                                          const LoadSlots& ls) {
    const int stage = t % STAGES;
    const __half* A = passA[t >> 4] + (t & 15) * BK;
    const __half* B = passB[t >> 4] + (t & 15) * BK;
    const uint32_t sa = smem0 + stage * STAGE_BYTES;
    const uint32_t sb = sa + BM * 128;
    #pragma unroll
    for (int i = 0; i < 4; i++) cp_async16(sa + ls.dst[i], A + ls.src[i]);
    #pragma unroll
    for (int i = 0; i < 4; i++) cp_async16(sb + ls.dst[i], B + ls.src[i]);
}

__global__ __launch_bounds__(256, 2) void gemm_kernel(float* __restrict__ out) {
    extern __shared__ __align__(128) char dsm[];
    const int tid  = threadIdx.x;
    const int lane = tid & 31;
    const int wid  = tid >> 5;
    const int wm   = wid & 1;       // 2 warps along M
    const int wn   = wid >> 1;      // 4 warps along N
    const int brow = blockIdx.y * BM;
    const int bcol = blockIdx.x * BN;

    const uint32_t smem0 = smem_to_u32(dsm);

    // cp.async slot mapping (identical for A and B halves of a stage):
    // 128 rows x 8 chunks(16B); 256 threads x 4 slots.
    LoadSlots ls;
    #pragma unroll
    for (int i = 0; i < 4; i++) {
        int idx = i * 256 + tid, r = idx >> 3, c = idx & 7;
        uint32_t off = (uint32_t)(r * 128 + c * 16);
        ls.dst[i] = off ^ ((off >> 3) & 0x70);
        ls.src[i] = r * D_DIM + c * 8;
    }

    const __half* passA[NPASS] = {g_qhi + (size_t)brow * D_DIM,
                                  g_qhi + (size_t)brow * D_DIM,
                                  g_qlo + (size_t)brow * D_DIM};
    const __half* passB[NPASS] = {g_phi + (size_t)bcol * D_DIM,
                                  g_plo + (size_t)bcol * D_DIM,
                                  g_phi + (size_t)bcol * D_DIM};

    // ldmatrix per-thread addressing.
    // A (16x16 tiles): lanes 0-15 -> rows, lanes 16-31 -> +16B (k8..15).
    const int a_row  = wm * 64 + (lane & 15);
    const uint32_t a_base = (uint32_t)(a_row * 128);
    const uint32_t a_xor  = (uint32_t)((a_row & 7) << 4);
    const uint32_t a_sel  = (lane & 16) ? 16u : 0u;
    // B (two n8 tiles per x4): lanes 0-7 n0-7/k0, 8-15 n0-7/k8, 16-23 n8-15/k0, 24-31 n8-15/k8.
    const int b_row  = wn * 32 + (lane & 7) + ((lane & 16) ? 8 : 0);
    const uint32_t b_base = (uint32_t)(BM * 128 + b_row * 128);
    const uint32_t b_xor  = (uint32_t)((b_row & 7) << 4);
    const uint32_t b_sel  = (lane & 8) ? 16u : 0u;

    float acc[4][4][4];
    #pragma unroll
    for (int i = 0; i < 4; i++)
        #pragma unroll
        for (int j = 0; j < 4; j++)
            #pragma unroll
            for (int k = 0; k < 4; k++) acc[i][j][k] = 0.0f;

    // Prologue: stages for tiles 0 .. STAGES-2
    #pragma unroll
    for (int t = 0; t < STAGES - 1; t++) {
        load_tile(t, smem0, passA, passB, ls);
        CP_COMMIT();
    }

    for (int t = 0; t < TOT_TILES; t++) {
        CP_WAIT(STAGES - 2);
        __syncthreads();

        const uint32_t sbase = smem0 + (t % STAGES) * STAGE_BYTES;
        #pragma unroll
        for (int ks = 0; ks < BK / 16; ks++) {
            uint32_t af[4][4], bf[2][4];
            #pragma unroll
            for (int mi = 0; mi < 4; mi++)
                ldsm_x4(af[mi], sbase + a_base + mi * 16 * 128 +
                                ((ks * 32 + a_sel) ^ a_xor));
            #pragma unroll
            for (int ni = 0; ni < 2; ni++)
                ldsm_x4(bf[ni], sbase + b_base + ni * 16 * 128 +
                                ((ks * 32 + b_sel) ^ b_xor));
            #pragma unroll
            for (int mi = 0; mi < 4; mi++)
                #pragma unroll
                for (int nj = 0; nj < 4; nj++)
                    mma16816(acc[mi][nj], af[mi], &bf[nj >> 1][(nj & 1) * 2]);
        }
        __syncthreads();

        if (t + STAGES - 1 < TOT_TILES)
            load_tile(t + STAGES - 1, smem0, passA, passB, ls);
        CP_COMMIT();
    }

    // Epilogue: c fragment -> out (raw qp; softmax pass applies 2*qp - p2).
    #pragma unroll
    for (int mi = 0; mi < 4; mi++) {
        #pragma unroll
        for (int nj = 0; nj < 4; nj++) {
            const int r = brow + wm * 64 + mi * 16 + (lane >> 2);
            const int c = bcol + wn * 32 + nj * 8 + (lane & 3) * 2;
            float* o0 = out + (size_t)r * M_DIM + c;
            float* o1 = out + (size_t)(r + 8) * M_DIM + c;
            *reinterpret_cast<float2*>(o0) = make_float2(acc[mi][nj][0], acc[mi][nj][1]);
            *reinterpret_cast<float2*>(o1) = make_float2(acc[mi][nj][2], acc[mi][nj][3]);
        }
    }
}

// ---------------------------------------------------------------------------
// Kernel D: in-place row softmax of s[m] = 2*qp[n,m] - p2[m].
// ---------------------------------------------------------------------------
__global__ __launch_bounds__(256) void softmax_kernel(float* __restrict__ out) {
    __shared__ float red[33];
    const int row = blockIdx.x;
    const int tid = threadIdx.x;
    float4* p = reinterpret_cast<float4*>(out + (size_t)row * M_DIM);

    float4 v  = p[tid];
    float4 pp = reinterpret_cast<const float4*>(g_p2)[tid];
    float s0 = 2.0f * v.x - pp.x, s1 = 2.0f * v.y - pp.y;
    float s2 = 2.0f * v.z - pp.z, s3 = 2.0f * v.w - pp.w;

    float m = fmaxf(fmaxf(s0, s1), fmaxf(s2, s3));
    #pragma unroll
    for (int o = 16; o; o >>= 1) m = fmaxf(m, __shfl_xor_sync(0xffffffffu, m, o));
    if ((tid & 31) == 0) red[tid >> 5] = m;
    __syncthreads();
    if (tid < 32) {
        float t = (tid < 8) ? red[tid] : -3.4e38f;
        #pragma unroll
        for (int o = 4; o; o >>= 1) t = fmaxf(t, __shfl_xor_sync(0xffffffffu, t, o));
        if (tid == 0) red[32] = t;
    }
    __syncthreads();
    const float rmax = red[32];

    float e0 = expf(s0 - rmax), e1 = expf(s1 - rmax);
    float e2 = expf(s2 - rmax), e3 = expf(s3 - rmax);
    float s = e0 + e1 + e2 + e3;
    #pragma unroll
    for (int o = 16; o; o >>= 1) s += __shfl_xor_sync(0xffffffffu, s, o);
    __syncthreads();
    if ((tid & 31) == 0) red[tid >> 5] = s;
    __syncthreads();
    if (tid < 32) {
        float t = (tid < 8) ? red[tid] : 0.0f;
        #pragma unroll
        for (int o = 4; o; o >>= 1) t += __shfl_xor_sync(0xffffffffu, t, o);
        if (tid == 0) red[32] = t;
    }
    __syncthreads();
    const float inv = 1.0f / red[32];
    p[tid] = make_float4(e0 * inv, e1 * inv, e2 * inv, e3 * inv);
}

// ---------------------------------------------------------------------------
extern "C" void kernel_launch(void* const* d_in, const int* in_sizes, int n_in,
                              void* d_out, int out_size) {
    const float* query = (const float*)d_in[0];   // [N, 1024] fp32
    const float* proto = (const float*)d_in[1];   // [1024, 1024] fp32
    float* out = (float*)d_out;                   // [N, 1024] fp32
    const int N = in_sizes[0] / D_DIM;

    cudaFuncSetAttribute(gemm_kernel, cudaFuncAttributeMaxDynamicSharedMemorySize,
                         SMEM_DYN_BYTES);

    convert_kernel<<<N + M_DIM, 256>>>(query, proto, N);
    p2_kernel<<<M_DIM, 256>>>(proto);

    dim3 grid(M_DIM / BN, N / BM);                // (8, 128)
    gemm_kernel<<<grid, 256, SMEM_DYN_BYTES>>>(out);

    softmax_kernel<<<N, 256>>>(out);
}

// round 4
// speedup vs baseline: 2.3954x; 1.0115x over previous
#include <cuda_runtime.h>
#include <cuda_fp16.h>
#include <cstdint>

#define D_DIM 1024
#define M_DIM 1024
#define N_MAX 16384

#define BM 128
#define BN 128
#define BK 64                       // halves per k-tile = 128 bytes/row
#define STAGES 3
#define KT_PER_PASS (D_DIM / BK)    // 16
#define NPASS 3
#define TOT_TILES (NPASS * KT_PER_PASS)  // 48

#define STAGE_BYTES (BM * 128 + BN * 128)   // 32 KB (A then B)
#define SMEM_DYN_BYTES (STAGES * STAGE_BYTES)

// ---------------- static device scratch (no allocation allowed) -------------
__device__ __align__(16) float  g_p2[M_DIM];
__device__ __align__(16) __half g_qhi[(size_t)N_MAX * D_DIM];
__device__ __align__(16) __half g_qlo[(size_t)N_MAX * D_DIM];
__device__ __align__(16) __half g_phi[(size_t)M_DIM * D_DIM];
__device__ __align__(16) __half g_plo[(size_t)M_DIM * D_DIM];

// ---------------- helpers ----------------------------------------------------
__device__ __forceinline__ uint32_t smem_to_u32(const void* p) {
    uint32_t a;
    asm("{ .reg .u64 t; cvta.to.shared.u64 t, %1; cvt.u32.u64 %0, t; }" : "=r"(a) : "l"(p));
    return a;
}

__device__ __forceinline__ void cp_async16(uint32_t dst, const void* src) {
    asm volatile("cp.async.cg.shared.global [%0], [%1], 16;" :: "r"(dst), "l"(src) : "memory");
}
#define CP_COMMIT() asm volatile("cp.async.commit_group;" ::: "memory")
#define CP_WAIT(n)  asm volatile("cp.async.wait_group %0;" :: "n"(n) : "memory")

__device__ __forceinline__ void ldsm_x4(uint32_t* r, uint32_t addr) {
    asm volatile("ldmatrix.sync.aligned.m8n8.x4.shared.b16 {%0,%1,%2,%3}, [%4];"
                 : "=r"(r[0]), "=r"(r[1]), "=r"(r[2]), "=r"(r[3]) : "r"(addr));
}

__device__ __forceinline__ void mma16816(float* c, const uint32_t* a, const uint32_t* b) {
    asm volatile(
        "mma.sync.aligned.m16n8k16.row.col.f32.f16.f16.f32 "
        "{%0,%1,%2,%3}, {%4,%5,%6,%7}, {%8,%9}, {%0,%1,%2,%3};"
        : "+f"(c[0]), "+f"(c[1]), "+f"(c[2]), "+f"(c[3])
        : "r"(a[0]), "r"(a[1]), "r"(a[2]), "r"(a[3]), "r"(b[0]), "r"(b[1]));
}

// ---------------------------------------------------------------------------
// Kernel A: split fp32 -> (hi, lo) fp16 pairs for Q and P.
// 4 rows per block; each thread does 4 independent float4 loads (MLP=4).
// ---------------------------------------------------------------------------
__global__ __launch_bounds__(256) void convert_kernel(const float* __restrict__ q,
                                                      const float* __restrict__ p, int nq) {
    const int row = blockIdx.x * 4 + (threadIdx.x >> 6);   // blocks never straddle Q/P
    const int cb  = threadIdx.x & 63;                       // 64 threads per row
    const bool isQ = row < nq;
    const float* src = isQ ? (q + (size_t)row * D_DIM) : (p + (size_t)(row - nq) * D_DIM);
    __half* dhi = isQ ? (g_qhi + (size_t)row * D_DIM) : (g_phi + (size_t)(row - nq) * D_DIM);
    __half* dlo = isQ ? (g_qlo + (size_t)row * D_DIM) : (g_plo + (size_t)(row - nq) * D_DIM);

    float4 v[4];
    #pragma unroll
    for (int j = 0; j < 4; j++)
        v[j] = reinterpret_cast<const float4*>(src)[cb + 64 * j];

    #pragma unroll
    for (int j = 0; j < 4; j++) {
        __half h0 = __float2half_rn(v[j].x), h1 = __float2half_rn(v[j].y);
        __half h2 = __float2half_rn(v[j].z), h3 = __float2half_rn(v[j].w);
        __half l0 = __float2half_rn(v[j].x - __half2float(h0));
        __half l1 = __float2half_rn(v[j].y - __half2float(h1));
        __half l2 = __float2half_rn(v[j].z - __half2float(h2));
        __half l3 = __float2half_rn(v[j].w - __half2float(h3));
        __half2 hv[2] = {__halves2half2(h0, h1), __halves2half2(h2, h3)};
        __half2 lv[2] = {__halves2half2(l0, l1), __halves2half2(l2, l3)};
        reinterpret_cast<uint2*>(dhi)[cb + 64 * j] = *reinterpret_cast<uint2*>(hv);
        reinterpret_cast<uint2*>(dlo)[cb + 64 * j] = *reinterpret_cast<uint2*>(lv);
    }
}

// ---------------------------------------------------------------------------
// Kernel B: p2[m] = sum_d proto[m,d]^2 (exact fp32). Warp per row, no barriers.
// ---------------------------------------------------------------------------
__global__ __launch_bounds__(256) void p2_kernel(const float* __restrict__ proto) {
    const int warp = threadIdx.x >> 5, lane = threadIdx.x & 31;
    const int m = blockIdx.x * 8 + warp;
    const float4* row = reinterpret_cast<const float4*>(proto + (size_t)m * D_DIM);
    float s = 0.0f;
    #pragma unroll
    for (int j = 0; j < 8; j++) {
        float4 v = row[lane + 32 * j];
        s += v.x * v.x + v.y * v.y + v.z * v.z + v.w * v.w;
    }
    #pragma unroll
    for (int o = 16; o; o >>= 1) s += __shfl_xor_sync(0xffffffffu, s, o);
    if (lane == 0) g_p2[m] = s;
}

// ---------------------------------------------------------------------------
// Kernel C: HMMA GEMM.  qp = Qhi*Phi^T + Qhi*Plo^T + Qlo*Phi^T  -> out
// 128x128 CTA tile, BK=64, 3-stage cp.async pipeline, ONE barrier per tile.
// ---------------------------------------------------------------------------
struct LoadSlots { uint32_t dst[4]; int src[4]; };

__device__ __forceinline__ void load_tile(int t, uint32_t smem0,
                                          const __half* const* passA,
                                          const __half* const* passB,
                                          const LoadSlots& ls) {
    const int stage = t % STAGES;
    const __half* A = passA[t >> 4] + (t & 15) * BK;
    const __half* B = passB[t >> 4] + (t & 15) * BK;
    const uint32_t sa = smem0 + stage * STAGE_BYTES;
    const uint32_t sb = sa + BM * 128;
    #pragma unroll
    for (int i = 0; i < 4; i++) cp_async16(sa + ls.dst[i], A + ls.src[i]);
    #pragma unroll
    for (int i = 0; i < 4; i++) cp_async16(sb + ls.dst[i], B + ls.src[i]);
}

__global__ __launch_bounds__(256, 2) void gemm_kernel(float* __restrict__ out) {
    extern __shared__ __align__(128) char dsm[];
    const int tid  = threadIdx.x;
    const int lane = tid & 31;
    const int wid  = tid >> 5;
    const int wm   = wid & 1;       // 2 warps along M
    const int wn   = wid >> 1;      // 4 warps along N
    const int brow = blockIdx.y * BM;
    const int bcol = blockIdx.x * BN;

    const uint32_t smem0 = smem_to_u32(dsm);

    LoadSlots ls;
    #pragma unroll
    for (int i = 0; i < 4; i++) {
        int idx = i * 256 + tid, r = idx >> 3, c = idx & 7;
        uint32_t off = (uint32_t)(r * 128 + c * 16);
        ls.dst[i] = off ^ ((off >> 3) & 0x70);
        ls.src[i] = r * D_DIM + c * 8;
    }

    const __half* passA[NPASS] = {g_qhi + (size_t)brow * D_DIM,
                                  g_qhi + (size_t)brow * D_DIM,
                                  g_qlo + (size_t)brow * D_DIM};
    const __half* passB[NPASS] = {g_phi + (size_t)bcol * D_DIM,
                                  g_plo + (size_t)bcol * D_DIM,
                                  g_phi + (size_t)bcol * D_DIM};

    // ldmatrix per-thread addressing (XOR-swizzled 128B rows).
    const int a_row  = wm * 64 + (lane & 15);
    const uint32_t a_base = (uint32_t)(a_row * 128);
    const uint32_t a_xor  = (uint32_t)((a_row & 7) << 4);
    const uint32_t a_sel  = (lane & 16) ? 16u : 0u;
    const int b_row  = wn * 32 + (lane & 7) + ((lane & 16) ? 8 : 0);
    const uint32_t b_base = (uint32_t)(BM * 128 + b_row * 128);
    const uint32_t b_xor  = (uint32_t)((b_row & 7) << 4);
    const uint32_t b_sel  = (lane & 8) ? 16u : 0u;

    float acc[4][4][4];
    #pragma unroll
    for (int i = 0; i < 4; i++)
        #pragma unroll
        for (int j = 0; j < 4; j++)
            #pragma unroll
            for (int k = 0; k < 4; k++) acc[i][j][k] = 0.0f;

    #pragma unroll
    for (int t = 0; t < STAGES - 1; t++) {
        load_tile(t, smem0, passA, passB, ls);
        CP_COMMIT();
    }

    for (int t = 0; t < TOT_TILES; t++) {
        CP_WAIT(STAGES - 2);
        __syncthreads();
        // Stage (t+2)%3 == stage of tile t-1, which every warp finished before
        // reaching the barrier above — safe to refill now, overlapping the MMAs.
        if (t + STAGES - 1 < TOT_TILES)
            load_tile(t + STAGES - 1, smem0, passA, passB, ls);
        CP_COMMIT();

        const uint32_t sbase = smem0 + (t % STAGES) * STAGE_BYTES;
        #pragma unroll
        for (int ks = 0; ks < BK / 16; ks++) {
            uint32_t af[4][4], bf[2][4];
            #pragma unroll
            for (int mi = 0; mi < 4; mi++)
                ldsm_x4(af[mi], sbase + a_base + mi * 16 * 128 +
                                ((ks * 32 + a_sel) ^ a_xor));
            #pragma unroll
            for (int ni = 0; ni < 2; ni++)
                ldsm_x4(bf[ni], sbase + b_base + ni * 16 * 128 +
                                ((ks * 32 + b_sel) ^ b_xor));
            #pragma unroll
            for (int mi = 0; mi < 4; mi++)
                #pragma unroll
                for (int nj = 0; nj < 4; nj++)
                    mma16816(acc[mi][nj], af[mi], &bf[nj >> 1][(nj & 1) * 2]);
        }
    }

    // Epilogue: store raw qp (softmax pass applies 2*qp - p2).
    #pragma unroll
    for (int mi = 0; mi < 4; mi++) {
        #pragma unroll
        for (int nj = 0; nj < 4; nj++) {
            const int r = brow + wm * 64 + mi * 16 + (lane >> 2);
            const int c = bcol + wn * 32 + nj * 8 + (lane & 3) * 2;
            float* o0 = out + (size_t)r * M_DIM + c;
            float* o1 = out + (size_t)(r + 8) * M_DIM + c;
            *reinterpret_cast<float2*>(o0) = make_float2(acc[mi][nj][0], acc[mi][nj][1]);
            *reinterpret_cast<float2*>(o1) = make_float2(acc[mi][nj][2], acc[mi][nj][3]);
        }
    }
}

// ---------------------------------------------------------------------------
// Kernel D: in-place row softmax of s[m] = 2*qp[n,m] - p2[m].
// Warp per row (8 rows / 256-thread block) -> zero block barriers.
// ---------------------------------------------------------------------------
__global__ __launch_bounds__(256) void softmax_kernel(float* __restrict__ out) {
    const int warp = threadIdx.x >> 5, lane = threadIdx.x & 31;
    const int row  = blockIdx.x * 8 + warp;
    float4* p = reinterpret_cast<float4*>(out + (size_t)row * M_DIM);
    const float4* pp = reinterpret_cast<const float4*>(g_p2);

    float s[32];
    #pragma unroll
    for (int j = 0; j < 8; j++) {
        float4 v = p[lane + 32 * j];
        float4 q = pp[lane + 32 * j];
        s[4 * j + 0] = 2.0f * v.x - q.x;
        s[4 * j + 1] = 2.0f * v.y - q.y;
        s[4 * j + 2] = 2.0f * v.z - q.z;
        s[4 * j + 3] = 2.0f * v.w - q.w;
    }

    float m = s[0];
    #pragma unroll
    for (int i = 1; i < 32; i++) m = fmaxf(m, s[i]);
    #pragma unroll
    for (int o = 16; o; o >>= 1) m = fmaxf(m, __shfl_xor_sync(0xffffffffu, m, o));

    float sum = 0.0f;
    #pragma unroll
    for (int i = 0; i < 32; i++) {
        s[i] = __expf(s[i] - m);
        sum += s[i];
    }
    #pragma unroll
    for (int o = 16; o; o >>= 1) sum += __shfl_xor_sync(0xffffffffu, sum, o);
    const float inv = 1.0f / sum;

    #pragma unroll
    for (int j = 0; j < 8; j++)
        p[lane + 32 * j] = make_float4(s[4 * j + 0] * inv, s[4 * j + 1] * inv,
                                       s[4 * j + 2] * inv, s[4 * j + 3] * inv);
}

// ---------------------------------------------------------------------------
extern "C" void kernel_launch(void* const* d_in, const int* in_sizes, int n_in,
                              void* d_out, int out_size) {
    const float* query = (const float*)d_in[0];   // [N, 1024] fp32
    const float* proto = (const float*)d_in[1];   // [1024, 1024] fp32
    float* out = (float*)d_out;                   // [N, 1024] fp32
    const int N = in_sizes[0] / D_DIM;

    cudaFuncSetAttribute(gemm_kernel, cudaFuncAttributeMaxDynamicSharedMemorySize,
                         SMEM_DYN_BYTES);

    convert_kernel<<<(N + M_DIM) / 4, 256>>>(query, proto, N);
    p2_kernel<<<M_DIM / 8, 256>>>(proto);

    dim3 grid(M_DIM / BN, N / BM);                // (8, 128)
    gemm_kernel<<<grid, 256, SMEM_DYN_BYTES>>>(out);

    softmax_kernel<<<N / 8, 256>>>(out);
}